// round 17
// baseline (speedup 1.0000x reference)
#include <cuda_runtime.h>
#include <math.h>

#define HH 512
#define WW 512
#define HWSZ (HH * WW)
#define EPSV 1e-8f

#define NP_MAX 256
#define UPP 32                 // 16-row units per plane
#define UROWS 16
#define NTHR 256
#define NW 8                   // warps per CTA
#define GRIDSZ (148 * 4)
#define PARTSZ 1026            // colS[512] colSS[512] ps pss
#define STATSZ 1026            // colM[512] colI[512] insM insI

__device__ float g_part[NP_MAX][UPP][PARTSZ];
__device__ float g_stats[NP_MAX][STATSZ];
__device__ unsigned int g_cnt1, g_cnt2, g_avail, g_pubSlot;
__device__ unsigned int g_done[NP_MAX];
__device__ int g_ready[NP_MAX];     // slot -> plane+1, in publication order

__global__ void init_kernel() {
    if (threadIdx.x == 0) { g_cnt1 = 0u; g_cnt2 = 0u; g_avail = 0u; g_pubSlot = 0u; }
    if (threadIdx.x < NP_MAX) { g_done[threadIdx.x] = 0u; g_ready[threadIdx.x] = 0; }
}

__device__ __forceinline__ float warp_sum(float v) {
#pragma unroll
    for (int o = 16; o > 0; o >>= 1) v += __shfl_xor_sync(0xffffffffu, v, o);
    return v;
}

__global__ __launch_bounds__(NTHR, 4) void ircn_pool(
    const float* __restrict__ in,
    const float* __restrict__ gRow_p, const float* __restrict__ bRow_p,
    const float* __restrict__ gCol_p, const float* __restrict__ bCol_p,
    const float* __restrict__ gIns_p, const float* __restrict__ bIns_p,
    float* __restrict__ out, int C, int nPlanes)
{
    __shared__ __align__(16) float sA[WW];   // stage1: colS accum | stage2: colM
    __shared__ __align__(16) float sB[WW];   // stage1: colSS accum | stage2: colI
    __shared__ float sWred[2 * NW];
    __shared__ int sKind;
    __shared__ unsigned sUnit;
    __shared__ int sPlane;
    __shared__ int sRed;

    const int tid = threadIdx.x;
    const int l = tid & 31;
    const int w = tid >> 5;
    const unsigned nU = (unsigned)(nPlanes * UPP);

    for (;;) {
        if (tid == 0) {
            int kind = 0; unsigned unit = 0;
            unsigned avail = *(volatile unsigned*)&g_avail;
            unsigned c2v = *(volatile unsigned*)&g_cnt2;
            // claim stage-2 only when safely behind publication (margin = grid size)
            if (c2v + GRIDSZ < avail) {
                unsigned u = atomicAdd(&g_cnt2, 1u);
                if (u < nU) { kind = 2; unit = u; }
            }
            if (kind == 0) {
                unsigned u = atomicAdd(&g_cnt1, 1u);
                if (u < nU) { kind = 1; unit = u; }
                else {
                    unsigned u2 = atomicAdd(&g_cnt2, 1u);   // drain phase
                    if (u2 < nU) { kind = 2; unit = u2; }
                }
            }
            sKind = kind; sUnit = unit;
        }
        __syncthreads();
        const int kind = sKind;
        const unsigned unit = sUnit;
        if (kind == 0) break;

        if (kind == 1) {
            // ================= Stage 1: stats + normRow from registers =========
            const int plane = (int)(unit >> 5);
            const int band = (int)(unit & 31u);
            const int c = plane % C;
            const int b = plane / C;
            const int r0 = band * UROWS;
            const float4* p4 = (const float4*)(in + (size_t)plane * HWSZ);

            sA[tid] = 0.f; sA[tid + 256] = 0.f;
            sB[tid] = 0.f; sB[tid + 256] = 0.f;

            const int rA = r0 + 2 * w;
            const int rB = rA + 1;
            float4 v0[4], v1[4];
#pragma unroll
            for (int k = 0; k < 4; k++) v0[k] = __ldcg(&p4[(size_t)rA * 128 + k * 32 + l]);
#pragma unroll
            for (int k = 0; k < 4; k++) v1[k] = __ldcg(&p4[(size_t)rB * 128 + k * 32 + l]);

            float s0 = 0.f, q0 = 0.f, s1 = 0.f, q1 = 0.f;
#pragma unroll
            for (int k = 0; k < 4; k++) {
                s0 += (v0[k].x + v0[k].y) + (v0[k].z + v0[k].w);
                q0 += v0[k].x * v0[k].x + v0[k].y * v0[k].y + v0[k].z * v0[k].z + v0[k].w * v0[k].w;
                s1 += (v1[k].x + v1[k].y) + (v1[k].z + v1[k].w);
                q1 += v1[k].x * v1[k].x + v1[k].y * v1[k].y + v1[k].z * v1[k].z + v1[k].w * v1[k].w;
            }
            s0 = warp_sum(s0); q0 = warp_sum(q0);
            s1 = warp_sum(s1); q1 = warp_sum(q1);

            const float m0 = s0 * (1.f / WW);
            const float i0 = 1.f / (sqrtf(fmaxf(q0 * (1.f / WW) - m0 * m0, 0.f) + EPSV) + EPSV);
            const float m1 = s1 * (1.f / WW);
            const float i1 = 1.f / (sqrtf(fmaxf(q1 * (1.f / WW) - m1 * m1, 0.f) + EPSV) + EPSV);

            // normRow straight from registers
            const float gR = gRow_p[c], bR = bRow_p[c];
            float* oR = out + (size_t)b * 3 * C * HWSZ + (size_t)(C + c) * HWSZ;
            float4* oRa = (float4*)(oR + (size_t)rA * WW);
            float4* oRb = (float4*)(oR + (size_t)rB * WW);
#pragma unroll
            for (int k = 0; k < 4; k++) {
                const int idx = k * 32 + l;
                float4 o;
                o.x = gR * (v0[k].x - m0) * i0 + bR;
                o.y = gR * (v0[k].y - m0) * i0 + bR;
                o.z = gR * (v0[k].z - m0) * i0 + bR;
                o.w = gR * (v0[k].w - m0) * i0 + bR;
                __stcs(&oRa[idx], o);
                o.x = gR * (v1[k].x - m1) * i1 + bR;
                o.y = gR * (v1[k].y - m1) * i1 + bR;
                o.z = gR * (v1[k].z - m1) * i1 + bR;
                o.w = gR * (v1[k].w - m1) * i1 + bR;
                __stcs(&oRb[idx], o);
            }

            if (l == 0) { sWred[w] = s0 + s1; sWred[NW + w] = q0 + q1; }
            __syncthreads();   // zeros + sWred complete

            // column partials (2-row combine in registers, then smem atomics)
#pragma unroll
            for (int k = 0; k < 4; k++) {
                const int cb = (k * 32 + l) * 4;
                float4 cs, cq;
                cs.x = v0[k].x + v1[k].x;  cq.x = v0[k].x * v0[k].x + v1[k].x * v1[k].x;
                cs.y = v0[k].y + v1[k].y;  cq.y = v0[k].y * v0[k].y + v1[k].y * v1[k].y;
                cs.z = v0[k].z + v1[k].z;  cq.z = v0[k].z * v0[k].z + v1[k].z * v1[k].z;
                cs.w = v0[k].w + v1[k].w;  cq.w = v0[k].w * v0[k].w + v1[k].w * v1[k].w;
                atomicAdd(&sA[cb + 0], cs.x); atomicAdd(&sA[cb + 1], cs.y);
                atomicAdd(&sA[cb + 2], cs.z); atomicAdd(&sA[cb + 3], cs.w);
                atomicAdd(&sB[cb + 0], cq.x); atomicAdd(&sB[cb + 1], cq.y);
                atomicAdd(&sB[cb + 2], cq.z); atomicAdd(&sB[cb + 3], cq.w);
            }
            __syncthreads();

            // export unit partials to fixed slots (deterministic)
            float* gp = &g_part[plane][band][0];
            gp[tid]        = sA[tid];
            gp[256 + tid]  = sA[256 + tid];
            gp[512 + tid]  = sB[tid];
            gp[768 + tid]  = sB[256 + tid];
            if (tid == 0) {
                float ps = 0.f, pq = 0.f;
#pragma unroll
                for (int i = 0; i < NW; i++) { ps += sWred[i]; pq += sWred[NW + i]; }
                gp[1024] = ps; gp[1025] = pq;
            }
            __syncthreads();

            if (tid == 0) {
                __threadfence();
                unsigned old = atomicAdd(&g_done[plane], 1u);
                sRed = (old == (unsigned)(UPP - 1));
            }
            __syncthreads();

            if (sRed) {
                // last finisher reduces the plane (fixed order -> deterministic)
                float sa = 0.f, qa = 0.f, sb = 0.f, qb = 0.f;
#pragma unroll 4
                for (int u = 0; u < UPP; u++) {
                    const float* pp = &g_part[plane][u][0];
                    sa += pp[tid];        qa += pp[512 + tid];
                    sb += pp[256 + tid];  qb += pp[768 + tid];
                }
                const float ma = sa * (1.f / HH);
                const float ia = 1.f / (sqrtf(fmaxf(qa * (1.f / HH) - ma * ma, 0.f) + EPSV) + EPSV);
                const float mb = sb * (1.f / HH);
                const float ib = 1.f / (sqrtf(fmaxf(qb * (1.f / HH) - mb * mb, 0.f) + EPSV) + EPSV);
                g_stats[plane][tid]        = ma;
                g_stats[plane][256 + tid]  = mb;
                g_stats[plane][512 + tid]  = ia;
                g_stats[plane][768 + tid]  = ib;
                if (tid == 0) {
                    float ps = 0.f, pq = 0.f;
                    for (int u = 0; u < UPP; u++) {
                        ps += g_part[plane][u][1024];
                        pq += g_part[plane][u][1025];
                    }
                    const float m = ps * (1.f / HWSZ);
                    g_stats[plane][1024] = m;
                    g_stats[plane][1025] =
                        1.f / (sqrtf(fmaxf(pq * (1.f / HWSZ) - m * m, 0.f) + EPSV) + EPSV);
                }
                __syncthreads();
                if (tid == 0) {
                    __threadfence();
                    unsigned slot = atomicAdd(&g_pubSlot, 1u);
                    atomicExch(&g_ready[slot], plane + 1);
                    __threadfence();
                    atomicAdd(&g_avail, (unsigned)UPP);
                }
            }
        } else {
            // ================= Stage 2: normIns + normCol ======================
            const unsigned slot = unit >> 5;
            const int band = (int)(unit & 31u);
            if (tid == 0) {
                int pl;
                while ((pl = *(volatile int*)&g_ready[slot]) == 0) __nanosleep(64);
                __threadfence();
                sPlane = pl - 1;
            }
            __syncthreads();
            const int plane = sPlane;
            const int c = plane % C;
            const int b = plane / C;
            const int r0 = band * UROWS;

            sA[tid]       = g_stats[plane][tid];          // colM
            sA[tid + 256] = g_stats[plane][256 + tid];
            sB[tid]       = g_stats[plane][512 + tid];    // colI
            sB[tid + 256] = g_stats[plane][768 + tid];
            __syncthreads();

            const float insM = g_stats[plane][1024];
            const float insI = g_stats[plane][1025];
            const float gI = gIns_p[c], bI = bIns_p[c];
            const float gC = gCol_p[c], bC = bCol_p[c];

            const float4* p4 = (const float4*)(in + (size_t)plane * HWSZ);
            const size_t outBase = (size_t)b * 3 * C * HWSZ;
            float* oI = out + outBase + (size_t)c * HWSZ;
            float* oC = out + outBase + (size_t)(2 * C + c) * HWSZ;
            const float4* cm4 = (const float4*)sA;
            const float4* ci4 = (const float4*)sB;

#pragma unroll
            for (int j = 0; j < 2; j++) {
                const int r = r0 + 2 * w + j;
                const float4* rp = &p4[(size_t)r * 128];
                float4* oIp = (float4*)(oI + (size_t)r * WW);
                float4* oCp = (float4*)(oC + (size_t)r * WW);
#pragma unroll
                for (int k = 0; k < 4; k++) {
                    const int idx = k * 32 + l;
                    float4 v = __ldcs(&rp[idx]);
                    float4 cm = cm4[idx];
                    float4 ci = ci4[idx];
                    float4 o;
                    o.x = gI * (v.x - insM) * insI + bI;
                    o.y = gI * (v.y - insM) * insI + bI;
                    o.z = gI * (v.z - insM) * insI + bI;
                    o.w = gI * (v.w - insM) * insI + bI;
                    __stcs(&oIp[idx], o);
                    o.x = gC * (v.x - cm.x) * ci.x + bC;
                    o.y = gC * (v.y - cm.y) * ci.y + bC;
                    o.z = gC * (v.z - cm.z) * ci.z + bC;
                    o.w = gC * (v.w - cm.w) * ci.w + bC;
                    __stcs(&oCp[idx], o);
                }
            }
        }
        __syncthreads();   // smem safe for next iteration
    }
}

extern "C" void kernel_launch(void* const* d_in, const int* in_sizes, int n_in,
                              void* d_out, int out_size) {
    const float* in = (const float*)d_in[0];
    const float* gRow = (const float*)d_in[1];
    const float* bRow = (const float*)d_in[2];
    const float* gCol = (const float*)d_in[3];
    const float* bCol = (const float*)d_in[4];
    const float* gIns = (const float*)d_in[5];
    const float* bIns = (const float*)d_in[6];
    float* out = (float*)d_out;

    const int C = in_sizes[1];                  // 128
    const int nPlanes = in_sizes[0] / HWSZ;     // B*C = 256

    init_kernel<<<1, 256>>>();
    ircn_pool<<<GRIDSZ, NTHR>>>(in, gRow, bRow, gCol, bCol, gIns, bIns,
                                out, C, nPlanes);
}